// round 4
// baseline (speedup 1.0000x reference)
#include <cuda_runtime.h>

// EMA scan h_t = a*x_t + (1-a)*h_{t-1}, T innermost. Warp-cooperative,
// fully coalesced. One warp per row; 32 tiles of 128 elems, processed in
// pairs for shuffle-chain ILP.
//
// R4: truncated Kogge-Stone (offsets 1,2,4 only — dropped terms weighted
// <= 0.6^32 ~ 8e-8, below existing fp32 noise) + 2-tile unroll (two
// independent scan chains in flight).

#define A    0.4f
#define OMA  0.6f
#define OMA2 0.36f
#define OMA3 0.216f
#define OMA4 0.1296f
#define FULL 0xFFFFFFFFu

__device__ __forceinline__ void tile_prefix(float4 v, float& s0, float& s1,
                                            float& s2, float& s3)
{
    s0 = A * v.x;
    s1 = fmaf(A, v.y, OMA * s0);
    s2 = fmaf(A, v.z, OMA * s1);
    s3 = fmaf(A, v.w, OMA * s2);
}

// truncated inclusive scan with decay 0.6^4 per lane (3 steps)
__device__ __forceinline__ float tile_scan(float s3, int lane)
{
    float I = s3;
    float u;
    u = __shfl_up_sync(FULL, I, 1);
    if (lane >= 1) I = fmaf(OMA4, u, I);                       // w = 0.6^4
    u = __shfl_up_sync(FULL, I, 2);
    if (lane >= 2) I = fmaf(0.01679616f, u, I);                // 0.6^8
    u = __shfl_up_sync(FULL, I, 4);
    if (lane >= 4) I = fmaf(2.82110990e-4f, u, I);             // 0.6^16
    return I;
}

__global__ void __launch_bounds__(256) ema_warp_kernel(
    const float* __restrict__ x,
    const float* __restrict__ h0,
    float* __restrict__ y,
    int T, int rows)
{
    int gwarp = (blockIdx.x * blockDim.x + threadIdx.x) >> 5;
    int lane  = threadIdx.x & 31;
    if (gwarp >= rows) return;

    const float4* xr = reinterpret_cast<const float4*>(x + (size_t)gwarp * T);
    float4*       yr = reinterpret_cast<float4*>(y + (size_t)gwarp * T);

    float h = h0[gwarp];

    float d4L = __powf(OMA4, (float)lane);      // 0.6^(4*lane)
    const float d128 = 2.4633073e-29f;          // 0.6^128

    int npairs = T / 256;
    for (int t = 0; t < npairs; t++) {
        // two independent tiles: loads + prefixes + scans all parallel
        float4 va = xr[t * 64 + lane];
        float4 vb = xr[t * 64 + 32 + lane];

        float a0, a1, a2, a3, b0, b1, b2, b3;
        tile_prefix(va, a0, a1, a2, a3);
        tile_prefix(vb, b0, b1, b2, b3);

        float Ia = tile_scan(a3, lane);
        float Ib = tile_scan(b3, lane);

        float Ba = __shfl_up_sync(FULL, Ia, 1); if (lane == 0) Ba = 0.0f;
        float Bb = __shfl_up_sync(FULL, Ib, 1); if (lane == 0) Bb = 0.0f;

        float I31a = __shfl_sync(FULL, Ia, 31);
        float I31b = __shfl_sync(FULL, Ib, 31);

        // tile a
        float Ca = fmaf(d4L, h, Ba);
        float4 oa;
        oa.x = fmaf(OMA,  Ca, a0);
        oa.y = fmaf(OMA2, Ca, a1);
        oa.z = fmaf(OMA3, Ca, a2);
        oa.w = fmaf(OMA4, Ca, a3);
        yr[t * 64 + lane] = oa;

        // carry into tile b
        float hm = fmaf(d128, h, I31a);

        float Cb = fmaf(d4L, hm, Bb);
        float4 ob;
        ob.x = fmaf(OMA,  Cb, b0);
        ob.y = fmaf(OMA2, Cb, b1);
        ob.z = fmaf(OMA3, Cb, b2);
        ob.w = fmaf(OMA4, Cb, b3);
        yr[t * 64 + 32 + lane] = ob;

        h = fmaf(d128, hm, I31b);
    }
}

extern "C" void kernel_launch(void* const* d_in, const int* in_sizes, int n_in,
                              void* d_out, int out_size)
{
    const float* x  = (const float*)d_in[0];   // inp    [B, D, T]
    const float* h0 = (const float*)d_in[1];   // hidden [B, D, 1]
    float* y = (float*)d_out;

    int rows = in_sizes[1];        // B*D = 8192
    int T = in_sizes[0] / rows;    // 4096

    int threads = 256;             // 8 warps/block -> 8 rows/block
    int blocks = (rows * 32 + threads - 1) / threads;
    ema_warp_kernel<<<blocks, threads>>>(x, h0, y, T, rows);
}